// round 16
// baseline (speedup 1.0000x reference)
#include <cuda_runtime.h>

#define NG   512
#define S    128
#define FENC 16777216.0          // 2^24 fixed-point encode grain
#define FDEC 8388608.0           // 2^23 decode: /2 gap applies pair-symmetry x2
#define CNT_BIT 54
#define SUM_MASK ((1ULL << CNT_BIT) - 1ULL)

__device__ unsigned long long g_acc = 0ULL;   // bits[0,54): fx sum, bits[54+): count

static __device__ __forceinline__ unsigned long long pk(float lo, float hi) {
    return (unsigned long long)__float_as_uint(lo)
         | ((unsigned long long)__float_as_uint(hi) << 32);
}

// 512 CTAs x 512 threads (4 CTAs/SM = HW max threads; ~16 warps/SMSP) with
// the PACKED f32x2 inner loop (fewest instr/pair measured: ~13 vs ~19):
// the two proven-good-but-individually-insufficient levers combined —
// r9 showed packed math cuts issue slots 30% (latency-starved at low occ),
// r14 showed high occupancy fills latency (issue-limited work remained).
//  * SMEM per row: ulonglong2 C = {(x0,t0),(x1,t1)}, u64 D = (x2,t2);
//    rows 0..63 duplicated so j=row+d needs no wraparound.
//  * thread (row=t&127, q=t>>7) covers d in [1+16q, 16+16q]; 15 unweighted
//    iterations + peeled 16th (d=16+16q; only q==3 hits d=64, weighted by
//    row<64 so each unordered pair counts once; x2 applied at decode).
//  * (sqrt a - sqrt b)^2 = a + b - 2*sqrt(ab), sqrt.approx (sqrt(0)=0
//    matches the grad-safe pdist).
//  * gather: threads<128 load both tensors' CA row (frame row 1 -> float
//    offset p*9+3); per-warp dtype ballot on odd dwords 129..191 (<1KB,
//    safe under both layouts: group-1 indices nonzero iff int32, zero int64
//    high-halves iff int64); int32-view positions load speculative.
//  * tail: ONE relaxed u64 atomicAdd packing {fx partial, arrival count}
//    (integer adds associative => deterministic); last CTA writes the mean
//    and resets the accumulator for graph replay.
__global__ void __launch_bounds__(512, 4)
loss_kernel(const float* __restrict__ inputs,
            const float* __restrict__ target,
            const void*  __restrict__ positions,
            float* __restrict__ out) {
    __shared__ ulonglong2         C[S + 64];
    __shared__ unsigned long long D[S + 64];
    __shared__ float              wsum[16];

    const int tid = threadIdx.x;
    const int g   = blockIdx.x;
    const int row = tid & (S - 1);
    const int q   = tid >> 7;          // 0..3

    // ---- gather (threads < 128): positions + both coordinate rows ----
    if (tid < S) {
        const unsigned* pw = (const unsigned*)positions;
        const unsigned p32 = pw[g * S + tid];                 // speculative
        const unsigned chk = pw[129 + 2 * (tid & 31)];        // <1KB, safe
        const unsigned any = __ballot_sync(0xffffffffu, chk != 0u);
        int p = (int)p32;
        if (any == 0u)                                        // int64 layout
            p = (int)((const long long*)positions)[g * S + tid];

        const float* xr = inputs + (size_t)p * 9 + 3;         // CA = frame row 1
        const float* tr = target + (size_t)p * 9 + 3;
        const ulonglong2 cv = make_ulonglong2(pk(xr[0], tr[0]), pk(xr[1], tr[1]));
        const unsigned long long dv = pk(xr[2], tr[2]);
        C[tid] = cv;  D[tid] = dv;
        if (tid < 64) { C[tid + S] = cv; D[tid + S] = dv; }
    }
    __syncthreads();

    // ---- own row, pre-negated packed ----
    const ulonglong2 ci = C[row];
    const unsigned long long di = D[row];
    const unsigned long long SGN = 0x8000000080000000ULL;
    const unsigned long long ni01 = ci.x ^ SGN;
    const unsigned long long ni23 = ci.y ^ SGN;
    const unsigned long long ni45 = di   ^ SGN;

    const ulonglong2*         Cj = &C[row + 1 + 16 * q];
    const unsigned long long* Dj = &D[row + 1 + 16 * q];

    unsigned long long accAB = 0ULL;   // packed (sumA, sumB)
    float accSq = 0.f;

#pragma unroll
    for (int jj = 0; jj < 15; ++jj) {
        const ulonglong2 v = Cj[jj];
        const unsigned long long v2 = Dj[jj];
        unsigned long long d0, d1, d2, ss;
        asm("add.rn.f32x2 %0, %1, %2;" : "=l"(d0) : "l"(v.x), "l"(ni01));
        asm("add.rn.f32x2 %0, %1, %2;" : "=l"(d1) : "l"(v.y), "l"(ni23));
        asm("add.rn.f32x2 %0, %1, %2;" : "=l"(d2) : "l"(v2),  "l"(ni45));
        asm("mul.rn.f32x2 %0, %1, %1;" : "=l"(ss) : "l"(d2));
        asm("fma.rn.f32x2 %0, %1, %1, %2;" : "=l"(ss) : "l"(d1), "l"(ss));
        asm("fma.rn.f32x2 %0, %1, %1, %2;" : "=l"(ss) : "l"(d0), "l"(ss));
        asm("add.rn.f32x2 %0, %1, %2;" : "=l"(accAB) : "l"(accAB), "l"(ss));
        float a, b;
        asm("mov.b64 {%0, %1}, %2;" : "=f"(a), "=f"(b) : "l"(ss));
        float sq;
        asm("sqrt.approx.f32 %0, %1;" : "=f"(sq) : "f"(a * b));
        accSq += sq;
    }

    float accA, accB;
    asm("mov.b64 {%0, %1}, %2;" : "=f"(accA), "=f"(accB) : "l"(accAB));

    // ---- peeled iteration jj=15: d = 16+16q; only q==3 hits d=64 ----
    {
        const float wLast = (q == 3 && row >= 64) ? 0.0f : 1.0f;
        const ulonglong2 v = Cj[15];
        const unsigned long long v2 = Dj[15];
        unsigned long long d0, d1, d2, ss;
        asm("add.rn.f32x2 %0, %1, %2;" : "=l"(d0) : "l"(v.x), "l"(ni01));
        asm("add.rn.f32x2 %0, %1, %2;" : "=l"(d1) : "l"(v.y), "l"(ni23));
        asm("add.rn.f32x2 %0, %1, %2;" : "=l"(d2) : "l"(v2),  "l"(ni45));
        asm("mul.rn.f32x2 %0, %1, %1;" : "=l"(ss) : "l"(d2));
        asm("fma.rn.f32x2 %0, %1, %1, %2;" : "=l"(ss) : "l"(d1), "l"(ss));
        asm("fma.rn.f32x2 %0, %1, %1, %2;" : "=l"(ss) : "l"(d0), "l"(ss));
        float a, b;
        asm("mov.b64 {%0, %1}, %2;" : "=f"(a), "=f"(b) : "l"(ss));
        float sq;
        asm("sqrt.approx.f32 %0, %1;" : "=f"(sq) : "f"(a * b));
        accA  = fmaf(wLast, a,  accA);
        accB  = fmaf(wLast, b,  accB);
        accSq = fmaf(wLast, sq, accSq);
    }

    float acc = (accA + accB) - 2.0f * accSq;

    // ---- block reduction (16 warps) ----
#pragma unroll
    for (int off = 16; off > 0; off >>= 1)
        acc += __shfl_xor_sync(0xffffffffu, acc, off);
    const int lane = tid & 31, warp = tid >> 5;
    if (lane == 0) wsum[warp] = acc;
    __syncthreads();

    // ---- single packed-atomic tail (tid 0 only) ----
    if (tid == 0) {
        float s = 0.0f;
#pragma unroll
        for (int w = 0; w < 16; ++w) s += wsum[w];
        s = fmaxf(s, 0.0f);                       // guard the count field
        const unsigned long long fx =
            (unsigned long long)(long long)((double)s * FENC);
        const unsigned long long add = fx + (1ULL << CNT_BIT);
        const unsigned long long old = atomicAdd(&g_acc, add);
        if ((old >> CNT_BIT) == (unsigned long long)(NG - 1)) {
            const unsigned long long tot = (old & SUM_MASK) + fx;
            out[0] = (float)((double)tot / FDEC / ((double)NG * S * S));
            g_acc = 0ULL;                          // reset for next replay
        }
    }
}

extern "C" void kernel_launch(void* const* d_in, const int* in_sizes, int n_in,
                              void* d_out, int out_size) {
    const float* inputs    = (const float*)d_in[0];
    const float* target    = (const float*)d_in[1];
    const void*  positions = d_in[2];
    loss_kernel<<<NG, 512>>>(inputs, target, positions, (float*)d_out);
}